// round 16
// baseline (speedup 1.0000x reference)
#include <cuda_runtime.h>
#include <cuda_bf16.h>

// Problem constants (fixed by the problem spec)
#define NS        4096
#define NQ_TOTAL  32768     // B * N_Q
#define KNN       8
#define FDIM      256
#define FDIM4     (FDIM/4)

// Grid: 20^3 cells of 0.44 over [-4.4, 4.4]; out-of-range coords clamp to edge
// cells (bound excludes domain-boundary faces, so clamping stays sound).
#define NC        20
#define NCELL     (NC*NC*NC)      // 8000
#define CS        0.44f
#define GLO       (-4.4f)

#define PTHREADS  128             // phase kernels: threads per block
#define CHUNK     8               // candidates per vote chunk
#define DEPTH     12              // smem buffer slots per thread
#define TRIG      4               // fold trigger (worst in-chunk slot = 3+8-1 = 10)
#define SLOTB     (PTHREADS*8)    // 1024 B between slots (shift 10)
#define SCAN_T    1024
#define SCAN_C    8
#define NEGINF    __int_as_float(0xff800000)
#define QNANF     __int_as_float(0x7fffffff)   // never passes setp.ge

// Device scratch (globals: allowed; no allocation)
__device__ int    g_scnt [NCELL];
__device__ int    g_sst  [NCELL + 1];
__device__ int    g_scur [NCELL];
__device__ int    g_scell[NS];
__device__ float4 g_ss   [NS];       // cell-sorted sensors (x, y, z, -0.5|s|^2)
__device__ int    g_so   [NS];       // sorted -> original sensor index
__device__ int    g_qcnt [NCELL];
__device__ int    g_qst  [NCELL + 1];
__device__ int    g_qcur [NCELL];
__device__ int    g_qcell[NQ_TOTAL];
__device__ float4 g_qs   [NQ_TOTAL]; // cell-sorted queries (x, y, z, orig-id bits)
__device__ int    g_acc  [NQ_TOTAL]; // 1 = result final
__device__ int    g_ri   [NQ_TOTAL * KNN];  // top-8 ORIGINAL sensor indices
__device__ float  g_w    [NQ_TOTAL * KNN];
__device__ int    g_idx  [NQ_TOTAL * KNN];

__device__ __forceinline__ int clampc(float v)
{
    return min(NC - 1, max(0, (int)floorf((v - GLO) / CS)));
}

// Composite comparator matching jax.lax.top_k: larger t wins; on exact t tie
// the SMALLER ORIGINAL index wins. Total order (orig unique per candidate).
__device__ __forceinline__ bool beats(float x, int xi, float vy, int iy)
{
    return (x > vy) || ((x == vy) && (xi < iy));
}

// Branchless tie-aware sorted insert of (t, orig) into descending top-8 list.
__device__ __forceinline__ void tie_insert(float x, int xi,
                                           float (&v)[KNN], int (&ii)[KNN])
{
#pragma unroll
    for (int j = KNN - 1; j >= 1; --j) {
        bool pjm = beats(x, xi, v[j-1], ii[j-1]);
        bool pj  = beats(x, xi, v[j],  ii[j]);
        v[j]  = pjm ? v[j-1]  : (pj ? x  : v[j]);
        ii[j] = pjm ? ii[j-1] : (pj ? xi : ii[j]);
    }
    bool p0 = beats(x, xi, v[0], ii[0]);
    v[0]  = p0 ? x  : v[0];
    ii[0] = p0 ? xi : ii[0];
}

// Fused predicated hit op. setp.GE so threshold-ties are buffered (resolved by
// original index at drain time). Invalid lanes pass NaN -> never stores.
__device__ __forceinline__ void score_op(unsigned& a, float t, float thr, float fi)
{
    asm volatile(
        "{\n\t"
        ".reg .pred p;\n\t"
        "setp.ge.f32 p, %1, %2;\n\t"
        "@p st.shared.v2.f32 [%0], {%1, %3};\n\t"
        "@p add.u32 %0, %0, %4;\n\t"
        "}"
        : "+r"(a)
        : "f"(t), "f"(thr), "f"(fi), "r"((unsigned)SLOTB)
        : "memory");
}

// ---------------------------------------------------------------------------
// Build kernels (sensor + query cell sort) — structure proven in R13
// ---------------------------------------------------------------------------
__global__ void kzero()
{
    int i = blockIdx.x * 256 + threadIdx.x;
    if (i < NCELL)          g_scnt[i]         = 0;
    else if (i < 2 * NCELL) g_qcnt[i - NCELL] = 0;
}

__global__ void kbin_s(const float* __restrict__ sc)
{
    int i = blockIdx.x * 256 + threadIdx.x;
    int c = (clampc(sc[3*i+2]) * NC + clampc(sc[3*i+1])) * NC + clampc(sc[3*i+0]);
    g_scell[i] = c;
    atomicAdd(&g_scnt[c], 1);
}

__global__ void kbin_q(const float* __restrict__ qc)
{
    int i = blockIdx.x * 256 + threadIdx.x;
    int c = (clampc(qc[3*i+2]) * NC + clampc(qc[3*i+1])) * NC + clampc(qc[3*i+0]);
    g_qcell[i] = c;
    atomicAdd(&g_qcnt[c], 1);
}

__global__ void __launch_bounds__(SCAN_T) kscan2()
{
    __shared__ int sh[SCAN_T];
    const int t  = threadIdx.x;
    const int c0 = t * SCAN_C;

    for (int which = 0; which < 2; which++) {
        int* cnt = which ? g_qcnt : g_scnt;
        int* st  = which ? g_qst  : g_sst;
        int* cur = which ? g_qcur : g_scur;

        int a[SCAN_C];
        int s = 0;
#pragma unroll
        for (int j = 0; j < SCAN_C; j++) {
            int c = c0 + j;
            a[j] = (c < NCELL) ? cnt[c] : 0;
            s += a[j];
        }
        sh[t] = s;
        __syncthreads();
        for (int off = 1; off < SCAN_T; off <<= 1) {
            int v = (t >= off) ? sh[t - off] : 0;
            __syncthreads();
            sh[t] += v;
            __syncthreads();
        }
        int excl = sh[t] - s;
#pragma unroll
        for (int j = 0; j < SCAN_C; j++) {
            int c = c0 + j;
            if (c < NCELL) { st[c] = excl; cur[c] = excl; }
            excl += a[j];
        }
        if (t == SCAN_T - 1) st[NCELL] = sh[SCAN_T - 1];
        __syncthreads();
    }
}

__global__ void kscat_s(const float* __restrict__ sc)
{
    int i = blockIdx.x * 256 + threadIdx.x;
    int p = atomicAdd(&g_scur[g_scell[i]], 1);
    float x = sc[3*i+0], y = sc[3*i+1], z = sc[3*i+2];
    g_ss[p] = make_float4(x, y, z, -0.5f * (x*x + y*y + z*z));
    g_so[p] = i;
}

__global__ void kscat_q(const float* __restrict__ qc)
{
    int i = blockIdx.x * 256 + threadIdx.x;
    int p = atomicAdd(&g_qcur[g_qcell[i]], 1);
    g_qs[p] = make_float4(qc[3*i+0], qc[3*i+1], qc[3*i+2], __int_as_float(i));
}

// ---------------------------------------------------------------------------
// Phase kernel (k = 1 or 2). Thread-per-query over cell-sorted queries.
// Exact top-8 within the (2k+1)^3 box (jax tie semantics via tie_insert on
// original indices); accepts iff the conservative face-distance bound
// guarantees global correctness (1e-3 slack also excludes out-of-box ties).
// ---------------------------------------------------------------------------
__global__ void __launch_bounds__(PTHREADS) kphase(int k, int use_acc)
{
    __shared__ float2 buf[DEPTH * PTHREADS];   // 12 KB

    const int tid = threadIdx.x;
    const int gid = blockIdx.x * PTHREADS + tid;

    const float4 Q = g_qs[gid];
    const float qx = Q.x, qy = Q.y, qz = Q.z;
    const float q2 = qx*qx + qy*qy + qz*qz;
    const int cx = clampc(qx), cy = clampc(qy), cz = clampc(qz);
    const int xlo = max(cx - k, 0), xhi = min(cx + k, NC - 1);

    const bool act = use_acc ? (g_acc[gid] == 0) : true;

    float v[KNN]; int ii[KNN];
#pragma unroll
    for (int j = 0; j < KNN; j++) { v[j] = NEGINF; ii[j] = 0x7fffffff; }

    const unsigned base = (unsigned)__cvta_generic_to_shared(buf) + tid * 8u;
    const unsigned lim  = base + TRIG * SLOTB;
    unsigned a   = base;
    float    thr = -3.0e38f;

    for (int dz = -k; dz <= k; dz++) {
        for (int dy = -k; dy <= k; dy++) {
            const int z = cz + dz, y = cy + dy;
            const bool okr = act && z >= 0 && z < NC && y >= 0 && y < NC;
            int start = 0, len = 0;
            if (okr) {
                const int rowb = (z * NC + y) * NC;
                start = g_sst[rowb + xlo];
                len   = g_sst[rowb + xhi + 1] - start;
            }
            for (int off = 0; ; off += CHUNK) {
                if (!__ballot_sync(0xffffffffu, off < len)) break;
#pragma unroll
                for (int u = 0; u < CHUNK; u++) {
                    const bool valid = (off + u) < len;
                    const int  idx   = valid ? (start + off + u) : 0;
                    float4 h = __ldg(&g_ss[idx]);
                    float tt = fmaf(qx, h.x, fmaf(qy, h.y, fmaf(qz, h.z, h.w)));
                    float t  = valid ? tt : QNANF;
                    score_op(a, t, thr, __int_as_float(idx));
                }
                if (__any_sync(0xffffffffu, a >= lim)) {
                    const int cnt = (int)((a - base) >> 10);
                    for (int j = 0; j < cnt; j++) {
                        float2 e  = buf[j * PTHREADS + tid];
                        const int orig = __ldg(&g_so[__float_as_int(e.y)]);
                        tie_insert(e.x, orig, v, ii);
                    }
                    a = base; thr = v[KNN-1];
                }
            }
        }
    }
    {   // final drain
        const int cnt = (int)((a - base) >> 10);
        for (int j = 0; j < cnt; j++) {
            float2 e  = buf[j * PTHREADS + tid];
            const int orig = __ldg(&g_so[__float_as_int(e.y)]);
            tie_insert(e.x, orig, v, ii);
        }
    }

    if (act) {
        bool accept = false;
        if (v[KNN-1] > -1.0e37f) {   // full 8 found inside the box
            const int ylo = max(cy - k, 0), yhi = min(cy + k, NC - 1);
            const int zlo = max(cz - k, 0), zhi = min(cz + k, NC - 1);
            float D = 1e30f;
            if (xlo > 0)    D = fminf(D, qx - (GLO + xlo * CS));
            if (xhi < NC-1) D = fminf(D, (GLO + (xhi + 1) * CS) - qx);
            if (ylo > 0)    D = fminf(D, qy - (GLO + ylo * CS));
            if (yhi < NC-1) D = fminf(D, (GLO + (yhi + 1) * CS) - qy);
            if (zlo > 0)    D = fminf(D, qz - (GLO + zlo * CS));
            if (zhi < NC-1) D = fminf(D, (GLO + (zhi + 1) * CS) - qz);
            const float Dm   = D - 1e-3f;
            const float d8sq = fmaxf(q2 - 2.0f * v[KNN-1], 0.0f);
            accept = (Dm > 0.0f) && (d8sq <= Dm * Dm);
        }
#pragma unroll
        for (int j = 0; j < KNN; j++) g_ri[gid * KNN + j] = ii[j];
        g_acc[gid] = accept ? 1 : 0;
    }
}

// ---------------------------------------------------------------------------
// Full-scan fallback for queries the bound could not certify (few %).
// ---------------------------------------------------------------------------
__global__ void __launch_bounds__(PTHREADS) kfull()
{
    __shared__ float2 buf[DEPTH * PTHREADS];

    const int tid = threadIdx.x;
    const int gid = blockIdx.x * PTHREADS + tid;

    const bool act = (g_acc[gid] == 0);
    if (!__ballot_sync(0xffffffffu, act)) return;   // whole warp done

    const float4 Q = g_qs[gid];
    const float qx = Q.x, qy = Q.y, qz = Q.z;

    float v[KNN]; int ii[KNN];
#pragma unroll
    for (int j = 0; j < KNN; j++) { v[j] = NEGINF; ii[j] = 0x7fffffff; }

    const unsigned base = (unsigned)__cvta_generic_to_shared(buf) + tid * 8u;
    const unsigned lim  = base + TRIG * SLOTB;
    unsigned a   = base;
    float    thr = -3.0e38f;
    const int len = act ? NS : 0;

    for (int off = 0; ; off += CHUNK) {
        if (!__ballot_sync(0xffffffffu, off < len)) break;
#pragma unroll
        for (int u = 0; u < CHUNK; u++) {
            const bool valid = (off + u) < len;
            const int  idx   = valid ? (off + u) : 0;
            float4 h = __ldg(&g_ss[idx]);
            float tt = fmaf(qx, h.x, fmaf(qy, h.y, fmaf(qz, h.z, h.w)));
            float t  = valid ? tt : QNANF;
            score_op(a, t, thr, __int_as_float(idx));
        }
        if (__any_sync(0xffffffffu, a >= lim)) {
            const int cnt = (int)((a - base) >> 10);
            for (int j = 0; j < cnt; j++) {
                float2 e  = buf[j * PTHREADS + tid];
                const int orig = __ldg(&g_so[__float_as_int(e.y)]);
                tie_insert(e.x, orig, v, ii);
            }
            a = base; thr = v[KNN-1];
        }
    }
    {   // final drain
        const int cnt = (int)((a - base) >> 10);
        for (int j = 0; j < cnt; j++) {
            float2 e  = buf[j * PTHREADS + tid];
            const int orig = __ldg(&g_so[__float_as_int(e.y)]);
            tie_insert(e.x, orig, v, ii);
        }
    }

    if (act) {
#pragma unroll
        for (int j = 0; j < KNN; j++) g_ri[gid * KNN + j] = ii[j];
    }
}

// ---------------------------------------------------------------------------
// Weights: exact distances from original coords (no cancellation), written to
// the ORIGINAL query index so gather stays unchanged.
// ---------------------------------------------------------------------------
__global__ void __launch_bounds__(256) kweights(const float* __restrict__ sc)
{
    const int gid = blockIdx.x * 256 + threadIdx.x;
    const float4 Q = g_qs[gid];
    const int origq = __float_as_int(Q.w);

    float w[KNN];
    int   so[KNN];
    float wsum = 0.0f;
#pragma unroll
    for (int j = 0; j < KNN; j++) {
        const int s = g_ri[gid * KNN + j];
        so[j] = s;
        float dx = Q.x - sc[3*s+0];
        float dy = Q.y - sc[3*s+1];
        float dz = Q.z - sc[3*s+2];
        float d  = sqrtf(fmaf(dx, dx, fmaf(dy, dy, dz*dz)));
        float wj = 1.0f / (d + 1e-8f);
        w[j] = wj;
        wsum += wj;
    }
    const float inv = 1.0f / wsum;
#pragma unroll
    for (int j = 0; j < KNN; j++) {
        g_w  [origq * KNN + j] = w[j] * inv;
        g_idx[origq * KNN + j] = so[j];
    }
}

// ---------------------------------------------------------------------------
// Gather kernel: weighted feature gather. One warp per query, coalesced float4.
// (At the L2 roofline: 268 MB of L2-resident reads ~ 21 us.)
// ---------------------------------------------------------------------------
__global__ void __launch_bounds__(256) gather_kernel(const float* __restrict__ feats,
                                                     float* __restrict__ out)
{
    const int gw   = (blockIdx.x * 256 + threadIdx.x) >> 5;
    const int lane = threadIdx.x & 31;
    const int b    = gw >> 13;

    const float4* __restrict__ fb =
        reinterpret_cast<const float4*>(feats) + (size_t)b * NS * FDIM4;

    float4 a0 = make_float4(0.f, 0.f, 0.f, 0.f);
    float4 a1 = make_float4(0.f, 0.f, 0.f, 0.f);

#pragma unroll
    for (int k = 0; k < KNN; k++) {
        const float wk = g_w  [gw*KNN + k];
        const int   id = g_idx[gw*KNN + k];
        const float4* __restrict__ fr = fb + (size_t)id * FDIM4;
        float4 f0 = fr[lane];
        float4 f1 = fr[lane + 32];
        a0.x = fmaf(wk, f0.x, a0.x); a0.y = fmaf(wk, f0.y, a0.y);
        a0.z = fmaf(wk, f0.z, a0.z); a0.w = fmaf(wk, f0.w, a0.w);
        a1.x = fmaf(wk, f1.x, a1.x); a1.y = fmaf(wk, f1.y, a1.y);
        a1.z = fmaf(wk, f1.z, a1.z); a1.w = fmaf(wk, f1.w, a1.w);
    }

    float4* __restrict__ o = reinterpret_cast<float4*>(out) + (size_t)gw * FDIM4;
    o[lane]      = a0;
    o[lane + 32] = a1;
}

// ---------------------------------------------------------------------------
// Launch: eleven dependent kernels, graph-capturable, allocation-free.
// ---------------------------------------------------------------------------
extern "C" void kernel_launch(void* const* d_in, const int* in_sizes, int n_in,
                              void* d_out, int out_size)
{
    const float* qc = (const float*)d_in[0];   // query_coords   (B, NQ, 3)
    const float* sc = (const float*)d_in[1];   // sensor_coords  (NS, 3)
    const float* ft = (const float*)d_in[2];   // sensor_features(B, NS, F)

    kzero        <<<(2 * NCELL + 255) / 256, 256>>>();
    kbin_s       <<<NS / 256, 256>>>(sc);
    kbin_q       <<<NQ_TOTAL / 256, 256>>>(qc);
    kscan2       <<<1, SCAN_T>>>();
    kscat_s      <<<NS / 256, 256>>>(sc);
    kscat_q      <<<NQ_TOTAL / 256, 256>>>(qc);
    kphase       <<<NQ_TOTAL / PTHREADS, PTHREADS>>>(1, 0);
    kphase       <<<NQ_TOTAL / PTHREADS, PTHREADS>>>(2, 1);
    kfull        <<<NQ_TOTAL / PTHREADS, PTHREADS>>>();
    kweights     <<<NQ_TOTAL / 256, 256>>>(sc);
    gather_kernel<<<(NQ_TOTAL * 32) / 256, 256>>>(ft, (float*)d_out);
}

// round 17
// speedup vs baseline: 9.9489x; 9.9489x over previous
#include <cuda_runtime.h>
#include <cuda_bf16.h>

// Problem constants (fixed by the problem spec)
#define NS        4096
#define NQ_TOTAL  32768     // B * N_Q
#define KNN       8
#define FDIM      256
#define FDIM4     (FDIM/4)

#define NSPLIT    4         // sensor quarters per query
#define QUARTER   1024      // sensors per block (NS / NSPLIT)
#define THREADS   256
#define QPT       2         // queries per thread
#define QPB       (THREADS*QPT)   // 512 queries per block-group
#define GROUP     16        // sensors per vote group (two 8-sensor phases)
#define PHASE     8         // sensors per compute phase (register pressure)
#define DEPTH     22        // smem candidate slots per (thread,query)
#define TRIG      6         // fold trigger (worst slot = 5+16 = 21 < 22)
#define SLOTB     (THREADS*8)     // 2048 B between buffer slots

// Inter-kernel scratch (device globals: allowed; no allocation)
__device__ float2 g_part[NSPLIT * KNN * NQ_TOTAL];  // [split][j][q], 8 MB
__device__ float  g_w  [NQ_TOTAL * KNN];
__device__ int    g_idx[NQ_TOTAL * KNN];

// Branchless sorted insert of (x, xi) into descending (value, idx) top-8 list.
// Strict '>' with original-index scan order == jax.lax.top_k tie semantics.
__device__ __forceinline__ void pair_insert(float x, int xi,
                                            float (&v)[KNN], int (&ii)[KNN])
{
#pragma unroll
    for (int j = KNN - 1; j >= 1; --j) {   // v[j-1] still old value here
        bool pjm = x > v[j-1];
        bool pj  = x > v[j];
        v[j]  = pjm ? v[j-1]  : (pj ? x  : v[j]);
        ii[j] = pjm ? ii[j-1] : (pj ? xi : ii[j]);
    }
    bool p0 = x > v[0];
    v[0]  = p0 ? x  : v[0];
    ii[0] = p0 ? xi : ii[0];
}

// Fused hit op: ONE compare feeds both the predicated store and the
// predicated cursor bump. 3 instructions, zero branches.
__device__ __forceinline__ void score_op(unsigned& a, float t, float thr, float fi)
{
    asm volatile(
        "{\n\t"
        ".reg .pred p;\n\t"
        "setp.gt.f32 p, %1, %2;\n\t"
        "@p st.shared.v2.f32 [%0], {%1, %3};\n\t"
        "@p add.u32 %0, %0, %4;\n\t"
        "}"
        : "+r"(a)
        : "f"(t), "f"(thr), "f"(fi), "r"((unsigned)SLOTB)
        : "memory");
}

// ---------------------------------------------------------------------------
// Scan kernel. Block = (query group of 512) x (sensor quarter of 1024).
// Each thread owns 2 queries; one broadcast LDS.128 feeds both dot products.
// Score t = q.s - 0.5|s|^2 (max == nearest). Hit handling is the fused
// 3-instruction predicated op. Warp-uniform folds (TRIG=6, larger/rarer)
// drain the smem buffer through a cheap reject filter into the
// register-resident sorted top-8 and tighten thr.
// ---------------------------------------------------------------------------
__global__ void __launch_bounds__(THREADS) scan_kernel(const float* __restrict__ qc,
                                                       const float* __restrict__ sc)
{
    extern __shared__ float4 tile[];                          // QUARTER*16B = 16 KB
    float2* buf0 = reinterpret_cast<float2*>(tile + QUARTER); // [DEPTH][THREADS] 44 KB
    float2* buf1 = buf0 + DEPTH * THREADS;                    // [DEPTH][THREADS] 44 KB

    const int tid    = threadIdx.x;
    const int split  = blockIdx.x & (NSPLIT - 1);
    const int qgroup = blockIdx.x >> 2;
    const int sbase  = split * QUARTER;
    const int q0     = qgroup * QPB + tid;
    const int q1     = q0 + THREADS;

    // Stage + preprocess this quarter's sensors: (x, y, z, 0.5*|s|^2)
    for (int i = tid; i < QUARTER; i += THREADS) {
        const int s = sbase + i;
        float sx = sc[3*s+0], sy = sc[3*s+1], sz = sc[3*s+2];
        tile[i] = make_float4(sx, sy, sz, 0.5f * (sx*sx + sy*sy + sz*sz));
    }
    __syncthreads();

    const float qx0 = qc[3*q0+0], qy0 = qc[3*q0+1], qz0 = qc[3*q0+2];
    const float qx1 = qc[3*q1+0], qy1 = qc[3*q1+1], qz1 = qc[3*q1+2];

    float v0[KNN], v1[KNN];
    int   i0[KNN], i1[KNN];
#pragma unroll
    for (int j = 0; j < KNN; j++) {
        v0[j] = -3.0e38f; i0[j] = 0;
        v1[j] = -3.0e38f; i1[j] = 0;
    }

    const unsigned base0 = (unsigned)__cvta_generic_to_shared(buf0) + tid * 8u;
    const unsigned base1 = (unsigned)__cvta_generic_to_shared(buf1) + tid * 8u;
    const unsigned lim0  = base0 + TRIG * SLOTB;
    const unsigned lim1  = base1 + TRIG * SLOTB;

    unsigned a0 = base0, a1 = base1;
    float thr0 = -3.0e38f, thr1 = -3.0e38f;

    for (int s0 = 0; s0 < QUARTER; s0 += GROUP) {
        // Two compute/store phases of 8 sensors (keeps live regs bounded)
#pragma unroll
        for (int ph = 0; ph < GROUP / PHASE; ph++) {
            const int pb = s0 + ph * PHASE;
            float t0[PHASE], t1[PHASE];
#pragma unroll
            for (int u = 0; u < PHASE; u++) {
                float4 h = tile[pb + u];
                t0[u] = fmaf(qx0, h.x, fmaf(qy0, h.y, fmaf(qz0, h.z, -h.w)));
                t1[u] = fmaf(qx1, h.x, fmaf(qy1, h.y, fmaf(qz1, h.z, -h.w)));
            }
#pragma unroll
            for (int u = 0; u < PHASE; u++) {
                const float fi = __int_as_float(sbase + pb + u);
                score_op(a0, t0[u], thr0, fi);
                score_op(a1, t1[u], thr1, fi);
            }
        }
        // Warp-uniform fold check once per 16 sensors (lanes stay converged:
        // all stores above are predicated single instructions)
        if (__any_sync(0xffffffffu, (a0 >= lim0) || (a1 >= lim1))) {
            const int cnt0 = (int)((a0 - base0) >> 11);
            const int cnt1 = (int)((a1 - base1) >> 11);
            for (int j = 0; j < cnt0; j++) {
                float2 e = buf0[j * THREADS + tid];
                if (e.x > v0[KNN-1])                       // reject filter
                    pair_insert(e.x, __float_as_int(e.y), v0, i0);
            }
            for (int j = 0; j < cnt1; j++) {
                float2 e = buf1[j * THREADS + tid];
                if (e.x > v1[KNN-1])
                    pair_insert(e.x, __float_as_int(e.y), v1, i1);
            }
            a0 = base0; a1 = base1;
            thr0 = v0[KNN-1]; thr1 = v1[KNN-1];
        }
    }
    // final drain
    {
        const int cnt0 = (int)((a0 - base0) >> 11);
        const int cnt1 = (int)((a1 - base1) >> 11);
        for (int j = 0; j < cnt0; j++) {
            float2 e = buf0[j * THREADS + tid];
            if (e.x > v0[KNN-1])
                pair_insert(e.x, __float_as_int(e.y), v0, i0);
        }
        for (int j = 0; j < cnt1; j++) {
            float2 e = buf1[j * THREADS + tid];
            if (e.x > v1[KNN-1])
                pair_insert(e.x, __float_as_int(e.y), v1, i1);
        }
    }

    // Publish sorted partial top-8s, coalesced [split][j][q] layout
#pragma unroll
    for (int j = 0; j < KNN; j++) {
        g_part[(split * KNN + j) * NQ_TOTAL + q0] =
            make_float2(v0[j], __int_as_float(i0[j]));
        g_part[(split * KNN + j) * NQ_TOTAL + q1] =
            make_float2(v1[j], __int_as_float(i1[j]));
    }
}

// ---------------------------------------------------------------------------
// Finalize: merge the four sorted quarters, exact distances (no cancellation),
// IDW weights. One thread per query.
// ---------------------------------------------------------------------------
__global__ void __launch_bounds__(256) finalize_kernel(const float* __restrict__ qc,
                                                       const float* __restrict__ sc)
{
    const int q = blockIdx.x * 256 + threadIdx.x;

    float v[KNN]; int ii[KNN];
#pragma unroll
    for (int j = 0; j < KNN; j++) {            // split 0 list already sorted desc
        float2 e = g_part[j * NQ_TOTAL + q];
        v[j]  = e.x;
        ii[j] = __float_as_int(e.y);
    }
#pragma unroll
    for (int sp = 1; sp < NSPLIT; sp++) {
#pragma unroll
        for (int j = 0; j < KNN; j++) {
            float2 e = g_part[(sp * KNN + j) * NQ_TOTAL + q];
            pair_insert(e.x, __float_as_int(e.y), v, ii);
        }
    }

    const float qx = qc[3*q+0];
    const float qy = qc[3*q+1];
    const float qz = qc[3*q+2];

    float w[KNN];
    float wsum = 0.0f;
#pragma unroll
    for (int j = 0; j < KNN; j++) {
        const int s = ii[j];
        float dx = qx - sc[3*s+0];
        float dy = qy - sc[3*s+1];
        float dz = qz - sc[3*s+2];
        float d  = sqrtf(fmaf(dx, dx, fmaf(dy, dy, dz*dz)));
        float wj = 1.0f / (d + 1e-8f);
        w[j] = wj;
        wsum += wj;
    }
    const float inv = 1.0f / wsum;
#pragma unroll
    for (int j = 0; j < KNN; j++) {
        g_w  [q*KNN + j] = w[j] * inv;
        g_idx[q*KNN + j] = ii[j];
    }
}

// ---------------------------------------------------------------------------
// Gather kernel: weighted feature gather. One warp per query, coalesced float4.
// (At the L2 roofline: 268 MB of L2-resident reads ~ its measured 21 us.)
// ---------------------------------------------------------------------------
__global__ void __launch_bounds__(256) gather_kernel(const float* __restrict__ feats,
                                                     float* __restrict__ out)
{
    const int gw   = (blockIdx.x * 256 + threadIdx.x) >> 5;  // global query id
    const int lane = threadIdx.x & 31;
    const int b    = gw >> 13;                               // / 8192

    const float4* __restrict__ fb =
        reinterpret_cast<const float4*>(feats) + (size_t)b * NS * FDIM4;

    float4 a0 = make_float4(0.f, 0.f, 0.f, 0.f);
    float4 a1 = make_float4(0.f, 0.f, 0.f, 0.f);

#pragma unroll
    for (int k = 0; k < KNN; k++) {
        const float wk = g_w  [gw*KNN + k];   // same addr across warp -> broadcast
        const int   id = g_idx[gw*KNN + k];
        const float4* __restrict__ fr = fb + (size_t)id * FDIM4;
        float4 f0 = fr[lane];
        float4 f1 = fr[lane + 32];
        a0.x = fmaf(wk, f0.x, a0.x); a0.y = fmaf(wk, f0.y, a0.y);
        a0.z = fmaf(wk, f0.z, a0.z); a0.w = fmaf(wk, f0.w, a0.w);
        a1.x = fmaf(wk, f1.x, a1.x); a1.y = fmaf(wk, f1.y, a1.y);
        a1.z = fmaf(wk, f1.z, a1.z); a1.w = fmaf(wk, f1.w, a1.w);
    }

    float4* __restrict__ o = reinterpret_cast<float4*>(out) + (size_t)gw * FDIM4;
    o[lane]      = a0;
    o[lane + 32] = a1;
}

// ---------------------------------------------------------------------------
// Launch: three dependent kernels, graph-capturable, allocation-free.
// ---------------------------------------------------------------------------
extern "C" void kernel_launch(void* const* d_in, const int* in_sizes, int n_in,
                              void* d_out, int out_size)
{
    const float* qc = (const float*)d_in[0];   // query_coords   (B, NQ, 3)
    const float* sc = (const float*)d_in[1];   // sensor_coords  (NS, 3)
    const float* ft = (const float*)d_in[2];   // sensor_features(B, NS, F)

    // 16 KB tile + 2 * 44 KB candidate buffers = 104 KB
    const int smem = QUARTER * 16 + 2 * DEPTH * THREADS * 8;

    cudaFuncSetAttribute(scan_kernel,
                         cudaFuncAttributeMaxDynamicSharedMemorySize, smem);

    scan_kernel    <<<(NQ_TOTAL / QPB) * NSPLIT, THREADS, smem>>>(qc, sc);
    finalize_kernel<<< NQ_TOTAL / 256, 256>>>(qc, sc);
    gather_kernel  <<<(NQ_TOTAL * 32) / 256, 256>>>(ft, (float*)d_out);
}